// round 15
// baseline (speedup 1.0000x reference)
#include <cuda_runtime.h>
#include <cuda_fp16.h>
#include <stdint.h>

// ---------------- problem constants ----------------
#define HID     2048
#define BATCHN  64
#define G4      8192
#define NSTEPS  30
#define NTILE   128           // M tiles of 64 gate-rows -> 128 CTAs (persistent)
#define NKCH    32            // K chunks of 64 fp16
#define WFCH    8192          // bytes per W chunk (64x64 fp16), both layouts
#define HCH     8192          // bytes per h chunk tile (64 batch x 128B, SW128)
#define NITER   16            // 2 chunks per iteration
#define RESCH   18            // W chunks resident in smem
#define SPLIT   9             // iters 0..SPLIT-1 resident, SPLIT..15 streamed LDG
#define RESBYTES (RESCH*8192) // 147456
#define HSTG    16384         // h stage = 2 chunks x 8K
#define NSTG    4
#define SMEM_REQ (RESBYTES + NSTG*HSTG + 1024)   // 214016

// ---------------- device scratch (static, no allocs) ----------------
__device__ __align__(1024) unsigned char g_wsumT[NTILE*NKCH*WFCH]; // tiled SW128 Wih+Whh
__device__ __align__(1024) unsigned char g_whhT [NTILE*NKCH*WFCH]; // tiled SW128 Whh
__device__ __align__(1024) unsigned char g_wsumF[NTILE*NKCH*WFCH]; // fragment-major (chunks>=RESCH)
__device__ __align__(1024) unsigned char g_whhF [NTILE*NKCH*WFCH];
__device__ __align__(1024) unsigned char g_hA[NKCH*HCH];
__device__ __align__(1024) unsigned char g_hB[NKCH*HCH];
__device__ float g_c[BATCHN*HID];
__device__ float g_bias[G4];
__device__ unsigned g_barrier;

// ---------------- helpers ----------------
__device__ __forceinline__ uint32_t smem_u32(const void* p) {
    uint32_t a;
    asm("{ .reg .u64 t; cvta.to.shared.u64 t, %1; cvt.u32.u64 %0, t; }" : "=r"(a) : "l"(p));
    return a;
}
__device__ __forceinline__ uint32_t swz(uint32_t o) { return o ^ ((o >> 3) & 0x70); }

__device__ __forceinline__ void ldm4(uint32_t* r, uint32_t a) {
    asm volatile("ldmatrix.sync.aligned.m8n8.x4.shared.b16 {%0,%1,%2,%3}, [%4];"
                 : "=r"(r[0]), "=r"(r[1]), "=r"(r[2]), "=r"(r[3]) : "r"(a));
}
__device__ __forceinline__ void mma16816(float* d, const uint32_t* a, uint32_t b0, uint32_t b1) {
    asm volatile("mma.sync.aligned.m16n8k16.row.col.f32.f16.f16.f32 "
                 "{%0,%1,%2,%3}, {%4,%5,%6,%7}, {%8,%9}, {%0,%1,%2,%3};"
                 : "+f"(d[0]), "+f"(d[1]), "+f"(d[2]), "+f"(d[3])
                 : "r"(a[0]), "r"(a[1]), "r"(a[2]), "r"(a[3]), "r"(b0), "r"(b1));
}
__device__ __forceinline__ void cp16(uint32_t dst, const void* src) {
    asm volatile("cp.async.cg.shared.global [%0], [%1], 16;" :: "r"(dst), "l"(src) : "memory");
}
#define CP_COMMIT() asm volatile("cp.async.commit_group;" ::: "memory")
__device__ __forceinline__ float sigm(float x) {
    x = fminf(15.f, fmaxf(-15.f, x));
    return 1.f / (1.f + __expf(-x));
}
__device__ __forceinline__ float tanh_(float x) {
    x = fminf(8.f, fmaxf(-8.f, x));
    float e = __expf(-2.f * x);
    return (1.f - e) / (1.f + e);
}

// ---------------- prep: BOTH layouts from one pass ----------------
// Chunk (blk, kc): logical 64x64 tile, rows r: gate=r>>4, u=r&15, orig row gate*HID+blk*16+u.
__global__ void prep_w(const float* __restrict__ Wih, const float* __restrict__ Whh) {
    __shared__ __half s_sum[64][66];
    __shared__ __half s_hh [64][66];
    int blk = blockIdx.x >> 5;
    int kc  = blockIdx.x & 31;
    int tid = threadIdx.x;

    int r = tid >> 2;
    int cb = (tid & 3) * 4;
    int gate = r >> 4, u = r & 15;
    long orow = (long)gate * HID + blk * 16 + u;
    const float* pi = Wih + orow * HID + kc * 64;
    const float* ph = Whh + orow * HID + kc * 64;
    #pragma unroll
    for (int j = 0; j < 4; j++) {
        int c = cb + j * 16;
        float4 a = *(const float4*)(pi + c);
        float4 b = *(const float4*)(ph + c);
        s_sum[r][c + 0] = __float2half_rn(a.x + b.x);
        s_sum[r][c + 1] = __float2half_rn(a.y + b.y);
        s_sum[r][c + 2] = __float2half_rn(a.z + b.z);
        s_sum[r][c + 3] = __float2half_rn(a.w + b.w);
        s_hh[r][c + 0] = __float2half_rn(b.x);
        s_hh[r][c + 1] = __float2half_rn(b.y);
        s_hh[r][c + 2] = __float2half_rn(b.z);
        s_hh[r][c + 3] = __float2half_rn(b.w);
    }
    __syncthreads();

    // tiled SW128 stores (all chunks)
    size_t tb = (size_t)(blk * NKCH + kc) * WFCH;
    #pragma unroll
    for (int it = 0; it < 8; it++) {
        int idx = it * 256 + tid;        // 0..2047 = (row, colpair)
        int cp = idx & 31, row = idx >> 5;
        uint32_t off = swz((uint32_t)(row * 128 + cp * 4));
        *(__half2*)(g_wsumT + tb + off) = __halves2half2(s_sum[row][cp * 2], s_sum[row][cp * 2 + 1]);
        *(__half2*)(g_whhT + tb + off)  = __halves2half2(s_hh[row][cp * 2],  s_hh[row][cp * 2 + 1]);
    }

    // fragment-major stores (streamed chunks only)
    if (kc >= RESCH) {
        size_t chbase = (size_t)(blk * NKCH + kc) * 512;   // 16B units
        #pragma unroll
        for (int it = 0; it < 2; it++) {
            int unit = it * 256 + tid;
            int kw   = unit >> 7;
            int wm   = (unit >> 6) & 1;
            int f    = (unit >> 5) & 1;
            int lane = unit & 31;
            int g = lane >> 2, t = lane & 3;
            int R0 = wm * 32 + f * 16 + g;
            int C0 = kw * 16 + 2 * t;
            uint4 vs, vh;
            vs.x = *(const uint32_t*)&s_sum[R0][C0];
            vs.y = *(const uint32_t*)&s_sum[R0 + 8][C0];
            vs.z = *(const uint32_t*)&s_sum[R0][C0 + 8];
            vs.w = *(const uint32_t*)&s_sum[R0 + 8][C0 + 8];
            vh.x = *(const uint32_t*)&s_hh[R0][C0];
            vh.y = *(const uint32_t*)&s_hh[R0 + 8][C0];
            vh.z = *(const uint32_t*)&s_hh[R0][C0 + 8];
            vh.w = *(const uint32_t*)&s_hh[R0 + 8][C0 + 8];
            ((uint4*)g_wsumF)[chbase + unit] = vs;
            ((uint4*)g_whhF)[chbase + unit]  = vh;
        }
    }
}

// zero c + barrier, fused bias, tiled fp16 h0, out initialized to b_out
__global__ void prep_misc(const float* __restrict__ tok,
                          const float* __restrict__ bih, const float* __restrict__ bhh,
                          const float* __restrict__ bout, float* __restrict__ out) {
    int id = blockIdx.x * 256 + threadIdx.x;      // 131072
    float h0 = tok[id];
    g_c[id] = 0.0f;
    int b = id >> 11, hid = id & 2047;
    int kc = hid >> 6, cc = hid & 63;
    uint32_t off = (uint32_t)kc * HCH + swz((uint32_t)(b * 128 + cc * 2));
    *(__half*)(g_hA + off) = __float2half_rn(h0);
    if (id < G4) g_bias[id] = bih[id] + bhh[id];
    if (id < BATCHN * NSTEPS) out[id] = bout[0];
    if (id == 0) g_barrier = 0u;
}

// ---------------- persistent kernel: all 30 steps, W resident in smem ----------------
#define SMX(g, b, u) smx[((g) * 64 + (b)) * 17 + (u)]

__global__ void __launch_bounds__(512, 1) lstm_persist(const float* __restrict__ Wout,
                                                       float* __restrict__ out) {
    extern __shared__ unsigned char smraw[];
    uint32_t sbr  = smem_u32(smraw);
    uint32_t base = (sbr + 1023) & ~1023u;
    uint32_t wres = base;                 // resident W, 18 chunks x 8KB
    uint32_t stg  = base + RESBYTES;      // h stages, 4 x 16KB
    float* smx = (float*)(smraw + (base - sbr) + RESBYTES);  // overlaps stages (dead at epilogue)

    int tid = threadIdx.x;
    int lane = tid & 31, wid = tid >> 5;
    int kw     = wid & 3;
    int warp_m = (wid >> 2) & 1;
    int warp_n = wid >> 3;
    int blk = blockIdx.x;

    float wout = Wout[blk * 16 + (tid & 15)];

    // W fragment LDG base offset within a chunk for this (kw, warp_m, lane)
    uint32_t wb = (uint32_t)kw * 2048 + (uint32_t)warp_m * 1024 + (uint32_t)lane * 16;
    // resident-A ldmatrix lane addresses (within a chunk)
    uint32_t kof    = (uint32_t)kw * 32;
    uint32_t a_colb = (uint32_t)((lane >> 4) << 4);
    uint32_t a_r0   = (uint32_t)(warp_m * 32 + (lane & 15));
    uint32_t aoff0  = swz(a_r0 * 128 + kof + a_colb);
    uint32_t aoff1  = swz((a_r0 + 16) * 128 + kof + a_colb);
    // h ldmatrix lane addresses
    uint32_t b_row  = (uint32_t)(warp_n * 32 + (lane & 7) + ((lane >> 4) << 3));
    uint32_t b_colb = (uint32_t)(((lane >> 3) & 1) << 4);

    int o = tid * 16;

    for (int step = 0; step < NSTEPS; step++) {
        const unsigned char* wT = ((step ? g_wsumT : g_whhT) + (size_t)blk * NKCH * WFCH);
        const unsigned char* wF = ((step ? g_wsumF : g_whhF) + (size_t)blk * NKCH * WFCH);
        const unsigned char* hsrc = (step & 1) ? g_hB : g_hA;
        unsigned char*       hout = (step & 1) ? g_hA : g_hB;

        // resident W (re)fill: Whh at step 0, Wsum at step 1; stable afterwards
        if (step < 2) {
            #pragma unroll
            for (int ch = 0; ch < RESCH; ch++)
                cp16(wres + ch * 8192 + o, wT + (size_t)ch * 8192 + o);
            CP_COMMIT();
            asm volatile("cp.async.wait_group 0;" ::: "memory");
            __syncthreads();
        }

        float acc[2][16];
        #pragma unroll
        for (int i = 0; i < 2; i++)
            #pragma unroll
            for (int j = 0; j < 16; j++) acc[i][j] = 0.f;

        // h prefetch stages 0..2 (chunks 0..5)
        #pragma unroll
        for (int s = 0; s < 3; s++) {
            uint32_t sb = stg + (uint32_t)s * HSTG;
            size_t gh = (size_t)(2 * s) * HCH;
            cp16(sb + o,        hsrc + gh + o);
            cp16(sb + 8192 + o, hsrc + gh + HCH + o);
            CP_COMMIT();
        }

        uint4 wc0, wc1, wc2, wc3, wn0, wn1, wn2, wn3;

        for (int kp = 0; kp < NITER; kp++) {
            // prefetch next-iter streamed W fragments (chunks 2(kp+1), 2(kp+1)+1)
            if (kp + 1 >= SPLIT && kp + 1 < NITER) {
                const unsigned char* p0 = wF + (size_t)(2 * (kp + 1)) * WFCH + wb;
                wn0 = *(const uint4*)(p0);
                wn1 = *(const uint4*)(p0 + 512);
                wn2 = *(const uint4*)(p0 + WFCH);
                wn3 = *(const uint4*)(p0 + WFCH + 512);
            }

            if (kp < NITER - 2)       asm volatile("cp.async.wait_group 2;" ::: "memory");
            else if (kp == NITER - 2) asm volatile("cp.async.wait_group 1;" ::: "memory");
            else                      asm volatile("cp.async.wait_group 0;" ::: "memory");
            __syncthreads();

            int np = kp + 3;
            if (np < NITER) {
                uint32_t sb = stg + (uint32_t)(np & 3) * HSTG;
                size_t gh = (size_t)(2 * np) * HCH;
                cp16(sb + o,        hsrc + gh + o);
                cp16(sb + 8192 + o, hsrc + gh + HCH + o);
                CP_COMMIT();
            }

            uint32_t sb = stg + (uint32_t)(kp & 3) * HSTG;
            uint32_t fb0[2][4], fb1[2][4];
            #pragma unroll
            for (int c = 0; c < 2; c++) {
                uint32_t sh = sb + (uint32_t)c * 8192;
                ldm4(fb0[c], sh + swz(b_row * 128 + kof + b_colb));
                ldm4(fb1[c], sh + swz((b_row + 16) * 128 + kof + b_colb));
            }
            if (kp < SPLIT) {
                // resident A: ldmatrix straight into the W frag registers
                uint32_t c0 = wres + (uint32_t)(2 * kp) * 8192;
                uint32_t c1 = c0 + 8192;
                ldm4((uint32_t*)&wc0, c0 + aoff0);
                ldm4((uint32_t*)&wc1, c0 + aoff1);
                ldm4((uint32_t*)&wc2, c1 + aoff0);
                ldm4((uint32_t*)&wc3, c1 + aoff1);
            }
            const uint32_t* a00 = (const uint32_t*)&wc0;
            const uint32_t* a01 = (const uint32_t*)&wc1;
            const uint32_t* a10 = (const uint32_t*)&wc2;
            const uint32_t* a11 = (const uint32_t*)&wc3;
            mma16816(acc[0] + 0,  a00, fb0[0][0], fb0[0][1]);
            mma16816(acc[0] + 4,  a00, fb0[0][2], fb0[0][3]);
            mma16816(acc[0] + 8,  a00, fb1[0][0], fb1[0][1]);
            mma16816(acc[0] + 12, a00, fb1[0][2], fb1[0][3]);
            mma16816(acc[1] + 0,  a01, fb0[0][0], fb0[0][1]);
            mma16816(acc[1] + 4,  a01, fb0[0][2], fb0[0][3]);
            mma16816(acc[1] + 8,  a01, fb1[0][0], fb1[0][1]);
            mma16816(acc[1] + 12, a01, fb1[0][2], fb1[0][3]);
            mma16816(acc[0] + 0,  a10, fb0[1][0], fb0[1][1]);
            mma16816(acc[0] + 4,  a10, fb0[1][2], fb0[1][3]);
            mma16816(acc[0] + 8,  a10, fb1[1][0], fb1[1][1]);
            mma16816(acc[0] + 12, a10, fb1[1][2], fb1[1][3]);
            mma16816(acc[1] + 0,  a11, fb0[1][0], fb0[1][1]);
            mma16816(acc[1] + 4,  a11, fb0[1][2], fb0[1][3]);
            mma16816(acc[1] + 8,  a11, fb1[1][0], fb1[1][1]);
            mma16816(acc[1] + 12, a11, fb1[1][2], fb1[1][3]);

            if (kp + 1 >= SPLIT) { wc0 = wn0; wc1 = wn1; wc2 = wn2; wc3 = wn3; }
        }
        __syncthreads();

        // ---- K-group reduction into smx[gate][batch][unit] (4 sequential rounds) ----
        #pragma unroll
        for (int r = 0; r < 4; r++) {
            if (kw == r) {
                #pragma unroll
                for (int mt = 0; mt < 2; mt++) {
                    int gate = warp_m * 2 + mt;
                    #pragma unroll
                    for (int g = 0; g < 4; g++) {
                        int n0 = warp_n * 32 + 8 * g + 2 * (lane & 3);
                        int u0 = lane >> 2;
                        if (r == 0) {
                            SMX(gate, n0,     u0    ) = acc[mt][4 * g + 0];
                            SMX(gate, n0 + 1, u0    ) = acc[mt][4 * g + 1];
                            SMX(gate, n0,     u0 + 8) = acc[mt][4 * g + 2];
                            SMX(gate, n0 + 1, u0 + 8) = acc[mt][4 * g + 3];
                        } else {
                            SMX(gate, n0,     u0    ) += acc[mt][4 * g + 0];
                            SMX(gate, n0 + 1, u0    ) += acc[mt][4 * g + 1];
                            SMX(gate, n0,     u0 + 8) += acc[mt][4 * g + 2];
                            SMX(gate, n0 + 1, u0 + 8) += acc[mt][4 * g + 3];
                        }
                    }
                }
            }
            __syncthreads();
        }

        // ---- fused LSTM cell + output projection: 16 units x 64 batch per CTA ----
        int kcb = blk >> 2;
        #pragma unroll
        for (int k = 0; k < 2; k++) {
            int p = k * 512 + tid;
            int u = p & 15, b = p >> 4;
            int hid = blk * 16 + u;
            float xi = SMX(0, b, u) + g_bias[hid];
            float xf = SMX(1, b, u) + g_bias[2048 + hid];
            float xg = SMX(2, b, u) + g_bias[4096 + hid];
            float xo = SMX(3, b, u) + g_bias[6144 + hid];
            float ii = sigm(xi), ff = sigm(xf), gg = tanh_(xg), oo = sigm(xo);
            int ci = b * HID + hid;
            float c = ff * g_c[ci] + ii * gg;
            g_c[ci] = c;
            float h = oo * tanh_(c);
            uint32_t off = (uint32_t)kcb * HCH +
                           swz((uint32_t)(b * 128 + ((blk & 3) * 16 + u) * 2));
            *(__half*)(hout + off) = __float2half_rn(h);
            float part = h * wout;
            #pragma unroll
            for (int s = 8; s; s >>= 1)
                part += __shfl_xor_sync(0xFFFFFFFFu, part, s);
            if ((lane & 15) == 0)
                atomicAdd(out + b * NSTEPS + step, part);
        }

        // ---- grid barrier: h of this step visible to all CTAs ----
        if (step < NSTEPS - 1) {
            __threadfence();
            __syncthreads();
            if (tid == 0) {
                atomicAdd(&g_barrier, 1u);
                unsigned target = 128u * (unsigned)(step + 1);
                while (*(volatile unsigned*)&g_barrier < target) __nanosleep(64);
                __threadfence();
            }
            __syncthreads();
        }
    }
}

// ---------------- launch ----------------
extern "C" void kernel_launch(void* const* d_in, const int* in_sizes, int n_in,
                              void* d_out, int out_size) {
    int wi = (n_in >= 8) ? 2 : 1;   // skip scalar `steps` input if present
    const float* tok  = (const float*)d_in[0];
    const float* Wih  = (const float*)d_in[wi];
    const float* Whh  = (const float*)d_in[wi + 1];
    const float* bih  = (const float*)d_in[wi + 2];
    const float* bhh  = (const float*)d_in[wi + 3];
    const float* Wout = (const float*)d_in[wi + 4];
    const float* bout = (const float*)d_in[wi + 5];
    float* out = (float*)d_out;

    cudaFuncSetAttribute(lstm_persist, cudaFuncAttributeMaxDynamicSharedMemorySize, SMEM_REQ);

    prep_w<<<NTILE * NKCH, 256>>>(Wih, Whh);
    prep_misc<<<512, 256>>>(tok, bih, bhh, bout, out);
    lstm_persist<<<NTILE, 512, SMEM_REQ>>>(Wout, out);
}

// round 17
// speedup vs baseline: 1.3436x; 1.3436x over previous
#include <cuda_runtime.h>
#include <cuda_fp16.h>
#include <stdint.h>

// ---------------- problem constants ----------------
#define HID     2048
#define BATCHN  64
#define G4      8192
#define NSTEPS  30
#define NTILE   128           // M tiles of 64 gate-rows -> 128 CTAs
#define NKCH    32            // K chunks of 64 fp16
#define WFCH    8192          // bytes per fragment-major W chunk (64x64 fp16)

// ---------------- device scratch (static, no allocs) ----------------
// Fragment-major W: unit (kc, kw, wm, f, lane) -> 16B = mma A regs a0..a3.
__device__ __align__(1024) unsigned char g_wsumF[NTILE*NKCH*WFCH]; // 32MB (Wih+Whh)
__device__ __align__(1024) unsigned char g_whhF [NTILE*NKCH*WFCH]; // 32MB (Whh, step 0)
// Fragment-major h: byte off = kc*8192 + kw*2048 + wn*1024 + half*512 + lane*16 + reg*4 + slot*2
__device__ __align__(1024) unsigned char g_hA[NKCH*8192];          // 256KB
__device__ __align__(1024) unsigned char g_hB[NKCH*8192];
__device__ float g_c[BATCHN*HID];
__device__ float g_bias[G4];

// ---------------- helpers ----------------
__device__ __forceinline__ void mma16816(float* d, const uint32_t* a, uint32_t b0, uint32_t b1) {
    asm volatile("mma.sync.aligned.m16n8k16.row.col.f32.f16.f16.f32 "
                 "{%0,%1,%2,%3}, {%4,%5,%6,%7}, {%8,%9}, {%0,%1,%2,%3};"
                 : "+f"(d[0]), "+f"(d[1]), "+f"(d[2]), "+f"(d[3])
                 : "r"(a[0]), "r"(a[1]), "r"(a[2]), "r"(a[3]), "r"(b0), "r"(b1));
}
__device__ __forceinline__ float sigm(float x) {
    x = fminf(15.f, fmaxf(-15.f, x));
    return 1.f / (1.f + __expf(-x));
}
__device__ __forceinline__ float tanh_(float x) {
    x = fminf(8.f, fmaxf(-8.f, x));
    float e = __expf(-2.f * x);
    return (1.f - e) / (1.f + e);
}

// ---------------- prep: fragment-major fp16 weights (all chunks) ----------------
// Chunk (blk, kc): logical 64x64 tile; rows r: gate=r>>4, u=r&15, orig row gate*HID+blk*16+u.
// Fragment unit (kw, wm, f, lane): a0 = (R0, C0..C0+1), a1 = (R0+8, C0..), a2 = (R0, C0+8..),
// a3 = (R0+8, C0+8..), R0 = wm*32+f*16+(lane>>2), C0 = kw*16+2*(lane&3).
__global__ void prep_w(const float* __restrict__ Wih, const float* __restrict__ Whh) {
    __shared__ __half s_sum[64][66];
    __shared__ __half s_hh [64][66];
    int blk = blockIdx.x >> 5;
    int kc  = blockIdx.x & 31;
    int tid = threadIdx.x;

    int r = tid >> 2;
    int cb = (tid & 3) * 4;
    int gate = r >> 4, u = r & 15;
    long orow = (long)gate * HID + blk * 16 + u;
    const float* pi = Wih + orow * HID + kc * 64;
    const float* ph = Whh + orow * HID + kc * 64;
    #pragma unroll
    for (int j = 0; j < 4; j++) {
        int c = cb + j * 16;
        float4 a = *(const float4*)(pi + c);
        float4 b = *(const float4*)(ph + c);
        s_sum[r][c + 0] = __float2half_rn(a.x + b.x);
        s_sum[r][c + 1] = __float2half_rn(a.y + b.y);
        s_sum[r][c + 2] = __float2half_rn(a.z + b.z);
        s_sum[r][c + 3] = __float2half_rn(a.w + b.w);
        s_hh[r][c + 0] = __float2half_rn(b.x);
        s_hh[r][c + 1] = __float2half_rn(b.y);
        s_hh[r][c + 2] = __float2half_rn(b.z);
        s_hh[r][c + 3] = __float2half_rn(b.w);
    }
    __syncthreads();

    size_t chbase = (size_t)(blk * NKCH + kc) * 512;   // 16B units
    #pragma unroll
    for (int it = 0; it < 2; it++) {
        int unit = it * 256 + tid;          // 0..511
        int kw   = unit >> 7;
        int wm   = (unit >> 6) & 1;
        int f    = (unit >> 5) & 1;
        int lane = unit & 31;
        int g = lane >> 2, t = lane & 3;
        int R0 = wm * 32 + f * 16 + g;
        int C0 = kw * 16 + 2 * t;
        uint4 vs, vh;
        vs.x = *(const uint32_t*)&s_sum[R0][C0];
        vs.y = *(const uint32_t*)&s_sum[R0 + 8][C0];
        vs.z = *(const uint32_t*)&s_sum[R0][C0 + 8];
        vs.w = *(const uint32_t*)&s_sum[R0 + 8][C0 + 8];
        vh.x = *(const uint32_t*)&s_hh[R0][C0];
        vh.y = *(const uint32_t*)&s_hh[R0 + 8][C0];
        vh.z = *(const uint32_t*)&s_hh[R0][C0 + 8];
        vh.w = *(const uint32_t*)&s_hh[R0 + 8][C0 + 8];
        ((uint4*)g_wsumF)[chbase + unit] = vs;
        ((uint4*)g_whhF)[chbase + unit]  = vh;
    }
}

// Fragment-major h address for value (hid, b); u = hid&15 within its 16-unit group.
__device__ __forceinline__ uint32_t h_frag_off(int hid, int b) {
    int u = hid & 15;
    return (uint32_t)(hid >> 4) * 2048 + (uint32_t)(b >> 5) * 1024 +
           (uint32_t)((b >> 4) & 1) * 512 +
           (uint32_t)((b & 7) * 4 + ((u & 7) >> 1)) * 16 +
           (uint32_t)(((b >> 3) & 1) * 2 + (u >> 3)) * 4 + (uint32_t)(u & 1) * 2;
}

// zero c, fused bias, fragment-major fp16 h0, out initialized to b_out
__global__ void prep_misc(const float* __restrict__ tok,
                          const float* __restrict__ bih, const float* __restrict__ bhh,
                          const float* __restrict__ bout, float* __restrict__ out) {
    int id = blockIdx.x * 256 + threadIdx.x;      // 131072
    float h0 = tok[id];
    g_c[id] = 0.0f;
    int b = id >> 11, hid = id & 2047;
    *(__half*)(g_hA + h_frag_off(hid, b)) = __float2half_rn(h0);
    if (id < G4) g_bias[id] = bih[id] + bhh[id];
    if (id < BATCHN * NSTEPS) out[id] = bout[0];
}

// ---------------- one LSTM step: zero-smem mainloop ----------------
// 512 threads, warp grid 2M x 2N x 4K. Per chunk per warp: 4 LDG.128 + 8 HMMA.
#define SMX(g, b, u) smx[((g) * 64 + (b)) * 17 + (u)]

__global__ void __launch_bounds__(512, 1) lstm_step(int step, const float* __restrict__ Wout,
                                                    float* __restrict__ out) {
    __shared__ float smx[4 * 64 * 17];

    int tid = threadIdx.x;
    int lane = tid & 31, wid = tid >> 5;
    int kw     = wid & 3;
    int warp_m = (wid >> 2) & 1;
    int warp_n = wid >> 3;
    int blk = blockIdx.x;

    const unsigned char* __restrict__ wf =
        (step ? g_wsumF : g_whhF) + (size_t)blk * NKCH * WFCH;
    const unsigned char* __restrict__ hf = (step & 1) ? g_hB : g_hA;
    unsigned char*       ho = (step & 1) ? g_hA : g_hB;

    float wout = Wout[blk * 16 + (tid & 15)];

    uint32_t wb = (uint32_t)kw * 2048 + (uint32_t)warp_m * 1024 + (uint32_t)lane * 16;
    uint32_t hb = (uint32_t)kw * 2048 + (uint32_t)warp_n * 1024 + (uint32_t)lane * 16;

    float acc[2][16];
    #pragma unroll
    for (int i = 0; i < 2; i++)
        #pragma unroll
        for (int j = 0; j < 16; j++) acc[i][j] = 0.f;

    uint4 wbuf[3][2], hbuf[3][2];
    #pragma unroll
    for (int p = 0; p < 2; p++) {
        const unsigned char* pw = wf + (uint32_t)p * 8192 + wb;
        const unsigned char* ph = hf + (uint32_t)p * 8192 + hb;
        wbuf[p][0] = *(const uint4*)pw;
        wbuf[p][1] = *(const uint4*)(pw + 512);
        hbuf[p][0] = *(const uint4*)ph;
        hbuf[p][1] = *(const uint4*)(ph + 512);
    }

    #pragma unroll
    for (int kc = 0; kc < NKCH; kc++) {
        int cur = kc % 3;
        if (kc + 2 < NKCH) {
            int nx = (kc + 2) % 3;
            const unsigned char* pw = wf + (uint32_t)(kc + 2) * 8192 + wb;
            const unsigned char* ph = hf + (uint32_t)(kc + 2) * 8192 + hb;
            wbuf[nx][0] = *(const uint4*)pw;
            wbuf[nx][1] = *(const uint4*)(pw + 512);
            hbuf[nx][0] = *(const uint4*)ph;
            hbuf[nx][1] = *(const uint4*)(ph + 512);
        }
        const uint32_t* a0 = (const uint32_t*)&wbuf[cur][0];
        const uint32_t* a1 = (const uint32_t*)&wbuf[cur][1];
        uint4 bl = hbuf[cur][0], bh = hbuf[cur][1];
        mma16816(acc[0] + 0,  a0, bl.x, bl.y);
        mma16816(acc[0] + 4,  a0, bl.z, bl.w);
        mma16816(acc[0] + 8,  a0, bh.x, bh.y);
        mma16816(acc[0] + 12, a0, bh.z, bh.w);
        mma16816(acc[1] + 0,  a1, bl.x, bl.y);
        mma16816(acc[1] + 4,  a1, bl.z, bl.w);
        mma16816(acc[1] + 8,  a1, bh.x, bh.y);
        mma16816(acc[1] + 12, a1, bh.z, bh.w);
    }
    __syncthreads();

    // ---- K-group reduction into smx[gate][batch][unit] (4 sequential rounds) ----
    #pragma unroll
    for (int r = 0; r < 4; r++) {
        if (kw == r) {
            #pragma unroll
            for (int mt = 0; mt < 2; mt++) {
                int gate = warp_m * 2 + mt;
                #pragma unroll
                for (int g = 0; g < 4; g++) {
                    int n0 = warp_n * 32 + 8 * g + 2 * (lane & 3);
                    int u0 = lane >> 2;
                    if (r == 0) {
                        SMX(gate, n0,     u0    ) = acc[mt][4 * g + 0];
                        SMX(gate, n0 + 1, u0    ) = acc[mt][4 * g + 1];
                        SMX(gate, n0,     u0 + 8) = acc[mt][4 * g + 2];
                        SMX(gate, n0 + 1, u0 + 8) = acc[mt][4 * g + 3];
                    } else {
                        SMX(gate, n0,     u0    ) += acc[mt][4 * g + 0];
                        SMX(gate, n0 + 1, u0    ) += acc[mt][4 * g + 1];
                        SMX(gate, n0,     u0 + 8) += acc[mt][4 * g + 2];
                        SMX(gate, n0 + 1, u0 + 8) += acc[mt][4 * g + 3];
                    }
                }
            }
        }
        __syncthreads();
    }

    // ---- fused LSTM cell + output projection: 16 units x 64 batch per CTA ----
    #pragma unroll
    for (int k = 0; k < 2; k++) {
        int p = k * 512 + tid;          // (unit, batch); u = tid&15 constant
        int u = p & 15, b = p >> 4;
        int hid = blk * 16 + u;
        float xi = SMX(0, b, u) + g_bias[hid];
        float xf = SMX(1, b, u) + g_bias[2048 + hid];
        float xg = SMX(2, b, u) + g_bias[4096 + hid];
        float xo = SMX(3, b, u) + g_bias[6144 + hid];
        float ii = sigm(xi), ff = sigm(xf), gg = tanh_(xg), oo = sigm(xo);
        int ci = b * HID + hid;
        float c = ff * g_c[ci] + ii * gg;
        g_c[ci] = c;
        float h = oo * tanh_(c);
        *(__half*)(ho + h_frag_off(hid, b)) = __float2half_rn(h);
        float part = h * wout;
        #pragma unroll
        for (int s = 8; s; s >>= 1)
            part += __shfl_xor_sync(0xFFFFFFFFu, part, s);
        if ((lane & 15) == 0)
            atomicAdd(out + b * NSTEPS + step, part);
    }
}

// ---------------- launch ----------------
extern "C" void kernel_launch(void* const* d_in, const int* in_sizes, int n_in,
                              void* d_out, int out_size) {
    int wi = (n_in >= 8) ? 2 : 1;   // skip scalar `steps` input if present
    const float* tok  = (const float*)d_in[0];
    const float* Wih  = (const float*)d_in[wi];
    const float* Whh  = (const float*)d_in[wi + 1];
    const float* bih  = (const float*)d_in[wi + 2];
    const float* bhh  = (const float*)d_in[wi + 3];
    const float* Wout = (const float*)d_in[wi + 4];
    const float* bout = (const float*)d_in[wi + 5];
    float* out = (float*)d_out;

    prep_w<<<NTILE * NKCH, 256>>>(Wih, Whh);
    prep_misc<<<512, 256>>>(tok, bih, bhh, bout, out);
    for (int t = 0; t < NSTEPS; t++)
        lstm_step<<<NTILE, 512>>>(t, Wout, out);
}